// round 7
// baseline (speedup 1.0000x reference)
#include <cuda_runtime.h>
#include <cuda_bf16.h>
#include <stdint.h>

#define OUT_CH    32
#define MAX_NODES 100000
#define CAP       128           // per-row bin capacity (Poisson(32): P(>128) ~ 0)
#define OVF_CAP   65536
#define MIN_BLOCKS 64

__device__ float g_Wt[MAX_NODES * OUT_CH];           // 12.8 MB transposed W
__device__ int   g_count[MAX_NODES];
__device__ int   g_bin[(size_t)MAX_NODES * CAP];     // 51.2 MB
__device__ int   g_part[MIN_BLOCKS];                 // row-min partials
__device__ int   g_ovf[2 * OVF_CAP];
__device__ int   g_ovf_cnt;

// ---------------------------------------------------------------------------
// K1 prep: blocks [0,NB): transpose W->Wt, zero g_count (+reset ovf cnt).
//          blocks [NB,NB+64): row-min partials -> g_part (plain stores).
// ---------------------------------------------------------------------------
__global__ void prep_kernel(const float* __restrict__ W, const int* __restrict__ rows,
                            int N, int E, int NB) {
    if ((int)blockIdx.x < NB) {
        int n = blockIdx.x * blockDim.x + threadIdx.x;
        if (n == 0) g_ovf_cnt = 0;
        if (n >= N) return;
        g_count[n] = 0;
        float v[OUT_CH];
        #pragma unroll
        for (int c = 0; c < OUT_CH; c++)
            v[c] = __ldg(&W[(size_t)c * N + n]);
        float4* dst = reinterpret_cast<float4*>(&g_Wt[(size_t)n * OUT_CH]);
        #pragma unroll
        for (int j = 0; j < OUT_CH / 4; j++)
            dst[j] = make_float4(v[4*j+0], v[4*j+1], v[4*j+2], v[4*j+3]);
    } else {
        __shared__ int s_wmin[8];
        int blk = blockIdx.x - NB;
        int i = blk * blockDim.x + threadIdx.x;
        int stride = MIN_BLOCKS * blockDim.x;
        int m = 0x7fffffff;
        for (; i < E; i += stride)
            m = min(m, __ldg(&rows[i]));
        #pragma unroll
        for (int off = 16; off > 0; off >>= 1)
            m = min(m, __shfl_xor_sync(0xffffffffu, m, off));
        if ((threadIdx.x & 31) == 0) s_wmin[threadIdx.x >> 5] = m;
        __syncthreads();
        if (threadIdx.x == 0) {
            int bm = s_wmin[0];
            #pragma unroll
            for (int k = 1; k < 8; k++) bm = min(bm, s_wmin[k]);
            g_part[blk] = bm;
        }
    }
}

// ---------------------------------------------------------------------------
// K2 fill: bucket cols by raw row. 4 edges per thread (strided), front-loaded
// index reads, 4 independent atomic->store chains.
// ---------------------------------------------------------------------------
__global__ void fill_kernel(const int* __restrict__ ei, int E, int N) {
    int Q = (E + 3) >> 2;
    int g = blockIdx.x * blockDim.x + threadIdx.x;
    if (g >= Q) return;
    int e0 = g, e1 = g + Q, e2 = g + 2*Q, e3 = g + 3*Q;
    bool h1 = e1 < E, h2 = e2 < E, h3 = e3 < E;

    int r0 = __ldg(&ei[e0]);
    int c0 = __ldg(&ei[E + e0]);
    int r1 = h1 ? __ldg(&ei[e1]) : -1;
    int c1 = h1 ? __ldg(&ei[E + e1]) : 0;
    int r2 = h2 ? __ldg(&ei[e2]) : -1;
    int c2 = h2 ? __ldg(&ei[E + e2]) : 0;
    int r3 = h3 ? __ldg(&ei[e3]) : -1;
    int c3 = h3 ? __ldg(&ei[E + e3]) : 0;

    bool k0 = (unsigned)r0 < (unsigned)N;
    bool k1 = (unsigned)r1 < (unsigned)N;
    bool k2 = (unsigned)r2 < (unsigned)N;
    bool k3 = (unsigned)r3 < (unsigned)N;

    int p0 = k0 ? atomicAdd(&g_count[r0], 1) : 0;
    int p1 = k1 ? atomicAdd(&g_count[r1], 1) : 0;
    int p2 = k2 ? atomicAdd(&g_count[r2], 1) : 0;
    int p3 = k3 ? atomicAdd(&g_count[r3], 1) : 0;

    if (k0) { if (p0 < CAP) g_bin[(size_t)r0 * CAP + p0] = c0;
              else { int x = atomicAdd(&g_ovf_cnt, 1); if (x < OVF_CAP) { g_ovf[2*x] = r0; g_ovf[2*x+1] = c0; } } }
    if (k1) { if (p1 < CAP) g_bin[(size_t)r1 * CAP + p1] = c1;
              else { int x = atomicAdd(&g_ovf_cnt, 1); if (x < OVF_CAP) { g_ovf[2*x] = r1; g_ovf[2*x+1] = c1; } } }
    if (k2) { if (p2 < CAP) g_bin[(size_t)r2 * CAP + p2] = c2;
              else { int x = atomicAdd(&g_ovf_cnt, 1); if (x < OVF_CAP) { g_ovf[2*x] = r2; g_ovf[2*x+1] = c2; } } }
    if (k3) { if (p3 < CAP) g_bin[(size_t)r3 * CAP + p3] = c3;
              else { int x = atomicAdd(&g_ovf_cnt, 1); if (x < OVF_CAP) { g_ovf[2*x] = r3; g_ovf[2*x+1] = c3; } } }
}

// ---------------------------------------------------------------------------
// K3 gather: one warp per output row n; sums Wt rows of bin(raw = n + minr).
// 8 columns in flight per iteration (2x int4 bin loads + 8 independent gathers).
// Writes full out incl. bias -> no init pass. No atomics.
// ---------------------------------------------------------------------------
__global__ void gather_kernel(float* __restrict__ out, const float* __restrict__ b,
                              int N) {
    __shared__ int s_min;
    if (threadIdx.x < 32) {
        int m = min(g_part[threadIdx.x], g_part[threadIdx.x + 32]);
        #pragma unroll
        for (int off = 16; off > 0; off >>= 1)
            m = min(m, __shfl_xor_sync(0xffffffffu, m, off));
        if (threadIdx.x == 0) s_min = m;
    }
    __syncthreads();
    int minr = s_min;

    int warp = (int)((blockIdx.x * blockDim.x + threadIdx.x) >> 5);
    int lane = threadIdx.x & 31;
    if (warp >= N) return;
    int raw = warp + minr;

    float acc = 0.f;
    if ((unsigned)raw < (unsigned)N) {
        int cnt = min(g_count[raw], CAP);
        const int* bb = &g_bin[(size_t)raw * CAP];
        int i = 0;
        for (; i + 8 <= cnt; i += 8) {
            int4 ca = *reinterpret_cast<const int4*>(bb + i);
            int4 cb = *reinterpret_cast<const int4*>(bb + i + 4);
            float a0 = __ldg(&g_Wt[(size_t)ca.x * OUT_CH + lane]);
            float a1 = __ldg(&g_Wt[(size_t)ca.y * OUT_CH + lane]);
            float a2 = __ldg(&g_Wt[(size_t)ca.z * OUT_CH + lane]);
            float a3 = __ldg(&g_Wt[(size_t)ca.w * OUT_CH + lane]);
            float a4 = __ldg(&g_Wt[(size_t)cb.x * OUT_CH + lane]);
            float a5 = __ldg(&g_Wt[(size_t)cb.y * OUT_CH + lane]);
            float a6 = __ldg(&g_Wt[(size_t)cb.z * OUT_CH + lane]);
            float a7 = __ldg(&g_Wt[(size_t)cb.w * OUT_CH + lane]);
            acc += ((a0 + a1) + (a2 + a3)) + ((a4 + a5) + (a6 + a7));
        }
        if (i + 4 <= cnt) {
            int4 ca = *reinterpret_cast<const int4*>(bb + i);
            float a0 = __ldg(&g_Wt[(size_t)ca.x * OUT_CH + lane]);
            float a1 = __ldg(&g_Wt[(size_t)ca.y * OUT_CH + lane]);
            float a2 = __ldg(&g_Wt[(size_t)ca.z * OUT_CH + lane]);
            float a3 = __ldg(&g_Wt[(size_t)ca.w * OUT_CH + lane]);
            acc += (a0 + a1) + (a2 + a3);
            i += 4;
        }
        for (; i < cnt; i++)
            acc += __ldg(&g_Wt[(size_t)bb[i] * OUT_CH + lane]);
    }
    out[(size_t)warp * OUT_CH + lane] = acc + __ldg(&b[lane]);
}

// ---------------------------------------------------------------------------
// K4 overflow fixup (expected empty). Runs after gather wrote out.
// ---------------------------------------------------------------------------
__global__ void ovf_kernel(float* __restrict__ out, int N) {
    __shared__ int s_min;
    if (threadIdx.x < 32) {
        int m = min(g_part[threadIdx.x], g_part[threadIdx.x + 32]);
        #pragma unroll
        for (int off = 16; off > 0; off >>= 1)
            m = min(m, __shfl_xor_sync(0xffffffffu, m, off));
        if (threadIdx.x == 0) s_min = m;
    }
    __syncthreads();
    int minr = s_min;

    int cnt = min(g_ovf_cnt, OVF_CAP);
    int tid = blockIdx.x * blockDim.x + threadIdx.x;
    int stride = gridDim.x * blockDim.x;
    for (int idx = tid; idx < cnt * 8; idx += stride) {
        int e = idx >> 3, t = idx & 7;
        int row = g_ovf[2*e] - minr;
        int col = g_ovf[2*e + 1];
        if ((unsigned)row >= (unsigned)N || (unsigned)col >= (unsigned)N) continue;
        float4 v = *reinterpret_cast<const float4*>(&g_Wt[(size_t)col * OUT_CH + t * 4]);
        float* dst = &out[(size_t)row * OUT_CH + t * 4];
        asm volatile("red.global.add.v4.f32 [%0], {%1, %2, %3, %4};"
                     :: "l"(dst), "f"(v.x), "f"(v.y), "f"(v.z), "f"(v.w) : "memory");
    }
}

// ---------------------------------------------------------------------------
extern "C" void kernel_launch(void* const* d_in, const int* in_sizes, int n_in,
                              void* d_out, int out_size) {
    const int*   ei = (const int*)d_in[0];     // [2, E]
    const float* W  = (const float*)d_in[1];   // [32, N]
    const float* b  = (const float*)d_in[2];   // [32]
    float* out = (float*)d_out;                // [N, 32]

    int E = in_sizes[0] / 2;
    int N = in_sizes[1] / OUT_CH;
    int threads = 256;

    int NB = (N + threads - 1) / threads;
    prep_kernel<<<NB + MIN_BLOCKS, threads>>>(W, ei, N, E, NB);

    int Q = (E + 3) >> 2;
    fill_kernel<<<(Q + threads - 1) / threads, threads>>>(ei, E, N);

    long long tw = (long long)N * 32;
    gather_kernel<<<(int)((tw + threads - 1) / threads), threads>>>(out, b, N);

    ovf_kernel<<<MIN_BLOCKS, threads>>>(out, N);
}

// round 8
// speedup vs baseline: 1.7606x; 1.7606x over previous
#include <cuda_runtime.h>
#include <cuda_bf16.h>
#include <stdint.h>

#define OUT_CH 32
#define MIN_BLOCKS 64

__device__ float g_Wt[100000 * OUT_CH];      // transposed W, L2-resident 12.8 MB
__device__ int   g_part[MIN_BLOCKS];         // row-min partials (fully rewritten each call)

// ---------------------------------------------------------------------------
// K1 (fused prep): blocks [0, NB): transpose W[32,N]->Wt[N,32] and out[n,:]=b.
//                  blocks [NB, NB+64): row-min partials -> g_part (plain stores).
// ---------------------------------------------------------------------------
__global__ void prep_kernel(const float* __restrict__ W, const float* __restrict__ b,
                            const int* __restrict__ rows, float* __restrict__ out,
                            int N, int E, int NB) {
    if ((int)blockIdx.x < NB) {
        int n = blockIdx.x * blockDim.x + threadIdx.x;
        if (n >= N) return;
        float v[OUT_CH];
        #pragma unroll
        for (int c = 0; c < OUT_CH; c++)
            v[c] = __ldg(&W[(size_t)c * N + n]);
        float4* dst = reinterpret_cast<float4*>(&g_Wt[(size_t)n * OUT_CH]);
        #pragma unroll
        for (int j = 0; j < OUT_CH / 4; j++)
            dst[j] = make_float4(v[4*j+0], v[4*j+1], v[4*j+2], v[4*j+3]);
        float4* o = reinterpret_cast<float4*>(&out[(size_t)n * OUT_CH]);
        #pragma unroll
        for (int j = 0; j < OUT_CH / 4; j++)
            o[j] = __ldg(reinterpret_cast<const float4*>(b) + j);
    } else {
        __shared__ int s_wmin[8];
        int blk = blockIdx.x - NB;                    // 0..63
        int i = blk * blockDim.x + threadIdx.x;
        int stride = MIN_BLOCKS * blockDim.x;
        int m = 0x7fffffff;
        for (; i < E; i += stride)
            m = min(m, __ldg(&rows[i]));
        #pragma unroll
        for (int off = 16; off > 0; off >>= 1)
            m = min(m, __shfl_xor_sync(0xffffffffu, m, off));
        if ((threadIdx.x & 31) == 0) s_wmin[threadIdx.x >> 5] = m;
        __syncthreads();
        if (threadIdx.x == 0) {
            int bm = s_wmin[0];
            #pragma unroll
            for (int k = 1; k < 8; k++) bm = min(bm, s_wmin[k]);
            g_part[blk] = bm;                         // plain store, no reset needed
        }
    }
}

// ---------------------------------------------------------------------------
// K2: scatter. 8 threads per edge-pair slot; each thread handles channel-quad t
// of TWO independent edges -> 2 independent LDG->RED chains (R4-proven config).
// ---------------------------------------------------------------------------
__global__ void scatter_kernel(const int* __restrict__ ei, int E, int N,
                               float* __restrict__ out) {
    // block-level rowmin reduction over the 64 partials (cheap, L2 broadcast)
    __shared__ int s_min;
    if (threadIdx.x < 32) {
        int m = min(g_part[threadIdx.x], g_part[threadIdx.x + 32]);
        #pragma unroll
        for (int off = 16; off > 0; off >>= 1)
            m = min(m, __shfl_xor_sync(0xffffffffu, m, off));
        if (threadIdx.x == 0) s_min = m;
    }
    __syncthreads();
    int minr = s_min;

    int half = (E + 1) >> 1;
    long long gtid = (long long)blockIdx.x * blockDim.x + threadIdx.x;
    long long g = gtid >> 3;
    int t = (int)(gtid & 7);
    if (g >= half) return;

    int e0 = (int)g;
    int e1 = e0 + half;
    bool has1 = (e1 < E);

    // front-load all index reads (independent)
    int row0 = __ldg(&ei[e0]);
    int col0 = __ldg(&ei[E + e0]);
    int row1 = has1 ? __ldg(&ei[e1]) : 0;
    int col1 = has1 ? __ldg(&ei[E + e1]) : 0;

    row0 -= minr;  row1 -= minr;
    bool ok0 = (unsigned)row0 < (unsigned)N && (unsigned)col0 < (unsigned)N;
    bool ok1 = has1 && (unsigned)row1 < (unsigned)N && (unsigned)col1 < (unsigned)N;

    // independent gathers (both in flight)
    float4 v0, v1;
    if (ok0) v0 = __ldg(reinterpret_cast<const float4*>(&g_Wt[(size_t)col0 * OUT_CH]) + t);
    if (ok1) v1 = __ldg(reinterpret_cast<const float4*>(&g_Wt[(size_t)col1 * OUT_CH]) + t);

    if (ok0) {
        float* dst = &out[(size_t)row0 * OUT_CH + t * 4];
        asm volatile("red.global.add.v4.f32 [%0], {%1, %2, %3, %4};"
                     :: "l"(dst), "f"(v0.x), "f"(v0.y), "f"(v0.z), "f"(v0.w) : "memory");
    }
    if (ok1) {
        float* dst = &out[(size_t)row1 * OUT_CH + t * 4];
        asm volatile("red.global.add.v4.f32 [%0], {%1, %2, %3, %4};"
                     :: "l"(dst), "f"(v1.x), "f"(v1.y), "f"(v1.z), "f"(v1.w) : "memory");
    }
}

// ---------------------------------------------------------------------------
extern "C" void kernel_launch(void* const* d_in, const int* in_sizes, int n_in,
                              void* d_out, int out_size) {
    const int*   ei = (const int*)d_in[0];     // [2, E]
    const float* W  = (const float*)d_in[1];   // [32, N]
    const float* b  = (const float*)d_in[2];   // [32]
    float* out = (float*)d_out;                // [N, 32]

    int E = in_sizes[0] / 2;
    int N = in_sizes[1] / OUT_CH;
    int threads = 256;

    int NB = (N + threads - 1) / threads;
    prep_kernel<<<NB + MIN_BLOCKS, threads>>>(W, b, ei, out, N, E, NB);

    long long half = (E + 1) >> 1;
    long long work = half * 8;
    int blocks = (int)((work + threads - 1) / threads);
    scatter_kernel<<<blocks, threads>>>(ei, E, N, out);
}